// round 1
// baseline (speedup 1.0000x reference)
#include <cuda_runtime.h>

// Problem constants (from reference):
//   t:          [P=4, B, C=256, L=3]  fp32
//   node_attrs: [B, Z=64]             fp32 one-hot
//   weights:    [Z=64, C=256, P=4]    fp32
//   out:        [B, C=256, L=3]       fp32
//   out[b,c,d] = ALPHA * sum_p W[z(b),c,p] * t[p,b,c,d],  z(b) = argmax one-hot
//   ALPHA = 1/sqrt(P) = 0.5 exactly

#define Z_DIM 64
#define C_DIM 256
#define P_DIM 4
#define L_DIM 3
#define CL    (C_DIM * L_DIM)   // 768 floats per (p,b) plane / per out row
#define CP    (C_DIM * P_DIM)   // 1024 floats per W[z] row
#define NTHR  (CL / 4)          // 192 threads: one float4 per thread

__global__ void __launch_bounds__(NTHR)
ecwl_kernel(const float* __restrict__ t,
            const float* __restrict__ na,
            const float* __restrict__ W,
            float*       __restrict__ out,
            int B)
{
    __shared__ int s_idx;

    const int b   = blockIdx.x;
    const int tid = threadIdx.x;

    // Resolve one-hot routing index for this node. Exactly one lane sees 1.0,
    // so the single shared write is race-free.
    if (tid < Z_DIM) {
        float v = na[(size_t)b * Z_DIM + tid];
        if (v > 0.5f) s_idx = tid;
    }
    __syncthreads();
    const int zi = s_idx;

    // Each thread owns elements e0..e0+3 of the flattened (c,d) plane (768
    // elems). Since d=3, a float4 straddles at most two consecutive c values.
    const int e0 = tid * 4;
    const int c0 = e0 / 3;

    // W[zi] row viewed as [C] float4 (the P=4 weights per channel, contiguous).
    const float4* __restrict__ Wr = reinterpret_cast<const float4*>(W + (size_t)zi * CP);
    const float4 w0 = __ldg(Wr + c0);       // weights for channel c0
    const float4 w1 = __ldg(Wr + c0 + 1);   // weights for channel c0+1 (c0 <= 254, safe)

    const float wA[4] = {w0.x, w0.y, w0.z, w0.w};
    const float wB[4] = {w1.x, w1.y, w1.z, w1.w};

    // Per-element channel-select mask (element i belongs to c0 or c0+1).
    const bool s1 = ((e0 + 1) / 3 == c0);
    const bool s2 = ((e0 + 2) / 3 == c0);
    const bool s3 = ((e0 + 3) / 3 == c0);

    float a0 = 0.f, a1 = 0.f, a2 = 0.f, a3 = 0.f;

    #pragma unroll
    for (int p = 0; p < P_DIM; ++p) {
        // Fully coalesced: 192 consecutive float4 = one contiguous 3072B span.
        const float4 v = *reinterpret_cast<const float4*>(
            t + ((size_t)p * B + b) * CL + e0);
        const float wa = wA[p];
        const float wb = wB[p];
        a0 += wa * v.x;
        a1 += (s1 ? wa : wb) * v.y;
        a2 += (s2 ? wa : wb) * v.z;
        a3 += (s3 ? wa : wb) * v.w;
    }

    float4 o;
    o.x = 0.5f * a0;   // ALPHA = 0.5 exact
    o.y = 0.5f * a1;
    o.z = 0.5f * a2;
    o.w = 0.5f * a3;
    reinterpret_cast<float4*>(out)[(size_t)b * NTHR + tid] = o;
}

extern "C" void kernel_launch(void* const* d_in, const int* in_sizes, int n_in,
                              void* d_out, int out_size)
{
    const float* t  = (const float*)d_in[0];   // [P,B,C,L]
    const float* na = (const float*)d_in[1];   // [B,Z]
    const float* W  = (const float*)d_in[2];   // [Z,C,P]
    float* out      = (float*)d_out;           // [B,C,L]

    const int B = in_sizes[1] / Z_DIM;

    ecwl_kernel<<<B, NTHR>>>(t, na, W, out, B);
}